// round 11
// baseline (speedup 1.0000x reference)
#include <cuda_runtime.h>
#include <cstdint>
#include <math.h>

#define DEPTH   14
#define LEAVES  16384
#define NNODES  32767
#define MEM     512
#define G3      1536
#define WORD    300
#define TAG     100
#define LEAF_IN 400
#define CH_IN   712

// ---------------- scratch (device globals) -----------------------------------
__device__ float g_states[(size_t)NNODES * MEM];
__device__ float g_Gi[(size_t)LEAVES * G3];           // right-child preacts (odd rows)
__device__ float g_H [(size_t)(LEAVES / 2) * MEM];    // h1
__device__ float g_H2[(size_t)(LEAVES / 2) * MEM];    // h2
__device__ float g_embsR[(size_t)LEAVES * WORD];
__device__ float g_tagsR[(size_t)NNODES * TAG];
__device__ float g_Wl [(size_t)G3 * LEAF_IN];
__device__ float g_Wci[(size_t)G3 * CH_IN];
__device__ float g_Wch[(size_t)G3 * MEM];
__device__ float g_Wn [(size_t)G3 * MEM];

__device__ __forceinline__ float sigmoidf(float x) { return 1.0f / (1.0f + expf(-x)); }

__device__ __forceinline__ uint32_t f2tf32(float x) {
    uint32_t r;
    asm("cvt.rna.tf32.f32 %0, %1;" : "=r"(r) : "f"(x));
    return r;
}
__device__ __forceinline__ void mma_tf32(float* c, const uint32_t* a, const uint32_t* b) {
    asm volatile(
        "mma.sync.aligned.m16n8k8.row.col.f32.tf32.tf32.f32 "
        "{%0,%1,%2,%3}, {%4,%5,%6,%7}, {%8,%9}, {%0,%1,%2,%3};"
        : "+f"(c[0]), "+f"(c[1]), "+f"(c[2]), "+f"(c[3])
        : "r"(a[0]), "r"(a[1]), "r"(a[2]), "r"(a[3]), "r"(b[0]), "r"(b[1]));
}
__device__ __forceinline__ void ldsm4(uint32_t* r, uint32_t addr) {
    asm volatile("ldmatrix.sync.aligned.m8n8.x4.shared.b16 {%0,%1,%2,%3}, [%4];"
                 : "=r"(r[0]), "=r"(r[1]), "=r"(r[2]), "=r"(r[3]) : "r"(addr));
}
__device__ __forceinline__ uint32_t smem_u32(const void* p) {
    uint32_t a;
    asm("{ .reg .u64 t; cvta.to.shared.u64 t, %1; cvt.u32.u64 %0, t; }" : "=r"(a) : "l"(p));
    return a;
}
__device__ __forceinline__ void cp16(uint32_t dst, const float* src, int sz) {
    asm volatile("cp.async.cg.shared.global [%0], [%1], 16, %2;"
                 :: "r"(dst), "l"(src), "r"(sz) : "memory");
}
#define CP_COMMIT() asm volatile("cp.async.commit_group;" ::: "memory")
#define CP_WAIT1()  asm volatile("cp.async.wait_group 1;" ::: "memory")

// ---------------- fused GEMM + GRU kernel (round-7 skeleton) --------------------
// 64-row x 64-gate-col tile; B tile = W rows {k, 512+k, 1024+k} (192 rows).
// MODE: 0=leaf, 1=ch_Wi (h1 even / gi odd), 2=ch_Wh (h2), 3=node_Wh (states).
#define AST      36
#define STAGE_B  36864u
#define BOFF     9216u
#define SMEM_SZ  (3 * 36864)

template<int MODE, int K>
__global__ __launch_bounds__(256, 2)
void gemm_gru(const float* __restrict__ Wr, const float* __restrict__ bi,
              const float* __restrict__ bh, int M, int nlvl, float* __restrict__ out) {
    extern __shared__ float sm[];
    constexpr int NC = (K + 31) / 32;

    const int tid  = threadIdx.x;
    const int lane = tid & 31;
    const int wid  = tid >> 5;
    const int gID  = lane >> 2, tq = lane & 3;
    const int wmRow = (wid >> 2) * 32;
    const int wk    = (wid & 3) * 16;
    const int gk0   = blockIdx.x * 64;
    const int bm    = blockIdx.y * 64;

    float acc[2][6][4];
    #pragma unroll
    for (int a = 0; a < 2; a++)
        #pragma unroll
        for (int b = 0; b < 6; b++)
            #pragma unroll
            for (int c = 0; c < 4; c++) acc[a][b][c] = 0.0f;

    const uint32_t smem_base = smem_u32(sm);
    const int rA0 = tid >> 3;
    const int cq  = (tid & 7) * 4;
    const uint32_t dstA0 = smem_base + 4u * (rA0 * AST + cq);
    const uint32_t dstB0 = smem_base + BOFF + 4u * (rA0 * AST + cq);
    uint32_t offB[6];
    #pragma unroll
    for (int it = 0; it < 6; it++) {
        int rB = rA0 + 32 * it;
        int grow = (rB >> 6) * MEM + gk0 + (rB & 63);
        offB[it] = (uint32_t)grow * K + cq;
    }

    uint32_t aAddr[2];
    #pragma unroll
    for (int mt = 0; mt < 2; mt++)
        aAddr[mt] = smem_base + 4u * ((wmRow + mt * 16 + (lane & 15)) * AST + (lane >> 4) * 4);
    uint32_t bAddr[3];
    #pragma unroll
    for (int g = 0; g < 3; g++)
        bAddr[g] = smem_base + BOFF +
                   4u * ((g * 64 + wk + ((lane >> 4) << 3) + (lane & 7)) * AST + ((lane >> 3) & 1) * 4);

    auto issueA = [&](int kc, uint32_t stN) {
        #pragma unroll
        for (int it = 0; it < 2; it++) {
            const int c4 = kc * 32 + cq;
            const int gm = bm + rA0 + 32 * it;
            const float* p = g_embsR;
            int sz = 0;
            if (MODE == 0) {
                if (gm < M) {
                    if (c4 < WORD)         { p = g_embsR + (size_t)gm * WORD + c4; sz = 16; }
                    else if (c4 < LEAF_IN) { p = g_tagsR + (size_t)(LEAVES - 1 + gm) * TAG + (c4 - WORD); sz = 16; }
                }
            } else if (MODE == 1) {
                if (gm < M) {
                    int pid = (gm >> 1) + nlvl - 1;
                    int ch  = 2 * pid + 1 + (gm & 1);
                    if (c4 < MEM)            { p = g_states + (size_t)ch * MEM + c4; sz = 16; }
                    else if (c4 < MEM + TAG) { p = g_tagsR + (size_t)ch * TAG + (c4 - MEM); sz = 16; }
                    else if (c4 < CH_IN)     { p = g_tagsR + (size_t)pid * TAG + (c4 - MEM - TAG); sz = 16; }
                }
            } else {
                const float* src = (MODE == 2) ? g_H : g_H2;
                if (gm < M && c4 < MEM) { p = src + (size_t)gm * MEM + c4; sz = 16; }
            }
            cp16(dstA0 + stN + it * 4608u, p, sz);
        }
    };
    auto issueB = [&](int kc, uint32_t stN) {
        const int c4 = kc * 32 + cq;
        const int sz = (c4 < K) ? 16 : 0;
        #pragma unroll
        for (int it = 0; it < 6; it++)
            cp16(dstB0 + stN + it * 4608u, Wr + offB[it] + (uint32_t)kc * 32u, sz);
    };

    issueA(0, 0u); issueB(0, 0u); CP_COMMIT();
    if (NC > 1) { issueA(1, STAGE_B); issueB(1, STAGE_B); }
    CP_COMMIT();

    // ---- register double-buffered fragments -----------------------------------
    uint32_t afr[2][2][4], bfr[2][3][4];
    auto ldfrag = [&](int buf, uint32_t kb) {
        ldsm4(afr[buf][0], aAddr[0] + kb);
        ldsm4(afr[buf][1], aAddr[1] + kb);
        ldsm4(bfr[buf][0], bAddr[0] + kb);
        ldsm4(bfr[buf][1], bAddr[1] + kb);
        ldsm4(bfr[buf][2], bAddr[2] + kb);
    };
    auto domma = [&](int buf) {
        #pragma unroll
        for (int mt = 0; mt < 2; mt++)
            #pragma unroll
            for (int g = 0; g < 3; g++) {
                mma_tf32(acc[mt][2 * g],     afr[buf][mt], bfr[buf][g]);
                mma_tf32(acc[mt][2 * g + 1], afr[buf][mt], bfr[buf][g] + 2);
            }
    };

    uint32_t stC = 0, stI = 2 * STAGE_B;
    #pragma unroll 1
    for (int kc = 0; kc < NC; kc++) {
        CP_WAIT1();
        __syncthreads();
        if (kc + 2 < NC) { issueA(kc + 2, stI); issueB(kc + 2, stI); }
        CP_COMMIT();
        ldfrag(0, stC);             // k8 = 0
        ldfrag(1, stC + 32u);       // k8 = 1 in flight
        domma(0);
        ldfrag(0, stC + 64u);       // k8 = 2 in flight behind k8=1's MMAs
        domma(1);
        ldfrag(1, stC + 96u);       // k8 = 3 in flight
        domma(0);
        domma(1);
        stC += STAGE_B; if (stC == 3 * STAGE_B) stC = 0;
        stI += STAGE_B; if (stI == 3 * STAGE_B) stI = 0;
    }

    // ---- fused epilogue ----
    #pragma unroll
    for (int mt = 0; mt < 2; mt++)
        #pragma unroll
        for (int kt = 0; kt < 2; kt++)
            #pragma unroll
            for (int j = 0; j < 4; j++) {
                int row = bm + wmRow + mt * 16 + gID + (j >> 1) * 8;
                if (row >= M) continue;
                int kcol = gk0 + wk + kt * 8 + 2 * tq + (j & 1);
                float aR = acc[mt][kt][j];
                float aZ = acc[mt][2 + kt][j];
                float aN = acc[mt][4 + kt][j];
                if (MODE == 0) {
                    float r  = sigmoidf(aR + bi[kcol] + bh[kcol]);
                    float z  = sigmoidf(aZ + bi[MEM + kcol] + bh[MEM + kcol]);
                    float nn = tanhf(aN + bi[2 * MEM + kcol] + r * bh[2 * MEM + kcol]);
                    g_states[(size_t)(LEAVES - 1 + row) * MEM + kcol] = (1.0f - z) * nn;
                } else if (MODE == 1) {
                    float giR = aR + bi[kcol], giZ = aZ + bi[MEM + kcol],
                          giN = aN + bi[2 * MEM + kcol];
                    if ((row & 1) == 0) {
                        float r  = sigmoidf(giR + bh[kcol]);
                        float z  = sigmoidf(giZ + bh[MEM + kcol]);
                        float nn = tanhf(giN + r * bh[2 * MEM + kcol]);
                        g_H[(size_t)(row >> 1) * MEM + kcol] = (1.0f - z) * nn;
                    } else {
                        float* d = g_Gi + (size_t)row * G3;
                        d[kcol] = giR; d[MEM + kcol] = giZ; d[2 * MEM + kcol] = giN;
                    }
                } else if (MODE == 2) {
                    const float* gi = g_Gi + (size_t)(2 * row + 1) * G3;
                    float r  = sigmoidf(gi[kcol] + aR + bh[kcol]);
                    float z  = sigmoidf(gi[MEM + kcol] + aZ + bh[MEM + kcol]);
                    float nn = tanhf(gi[2 * MEM + kcol] + r * (aN + bh[2 * MEM + kcol]));
                    g_H2[(size_t)row * MEM + kcol] =
                        (1.0f - z) * nn + z * g_H[(size_t)row * MEM + kcol];
                } else {
                    float r  = sigmoidf(bi[kcol] + aR + bh[kcol]);
                    float z  = sigmoidf(bi[MEM + kcol] + aZ + bh[MEM + kcol]);
                    float nn = tanhf(bi[2 * MEM + kcol] + r * (aN + bh[2 * MEM + kcol]));
                    float st = (1.0f - z) * nn + z * g_H2[(size_t)row * MEM + kcol];
                    g_states[(size_t)(row + nlvl - 1) * MEM + kcol] = st;
                    if (nlvl == 1) out[kcol] = st;
                }
            }
}

// ---------------- prep: round weights/embs/tags to tf32 once --------------------
#define N_EMB (LEAVES * WORD)
#define N_TAG (NNODES * TAG)
#define N_WL  (G3 * LEAF_IN)
#define N_WCI (G3 * CH_IN)
#define N_WCH (G3 * MEM)
#define N_TOT ((int64_t)N_EMB + N_TAG + N_WL + N_WCI + 2 * N_WCH)

__global__ void prep_round(const float* __restrict__ embs, const float* __restrict__ tags,
                           const float* __restrict__ lw, const float* __restrict__ cwi,
                           const float* __restrict__ cwh, const float* __restrict__ nw) {
    int64_t i = blockIdx.x * (int64_t)blockDim.x + threadIdx.x;
    int64_t stride = (int64_t)gridDim.x * blockDim.x;
    for (; i < N_TOT; i += stride) {
        int64_t j = i;
        const float* s; float* d;
        if (j < N_EMB)               { s = embs; d = g_embsR; }
        else if ((j -= N_EMB) < N_TAG) { s = tags; d = g_tagsR; }
        else if ((j -= N_TAG) < N_WL)  { s = lw;   d = g_Wl; }
        else if ((j -= N_WL) < N_WCI)  { s = cwi;  d = g_Wci; }
        else if ((j -= N_WCI) < N_WCH) { s = cwh;  d = g_Wch; }
        else { j -= N_WCH;              s = nw;   d = g_Wn; }
        d[j] = __uint_as_float(f2tf32(s[j]));
    }
}

// ---------------- host driver ------------------------------------------------
extern "C" void kernel_launch(void* const* d_in, const int* in_sizes, int n_in,
                              void* d_out, int out_size) {
    const float* embs    = (const float*)d_in[0];
    const float* tags    = (const float*)d_in[1];
    const float* leaf_Wi = (const float*)d_in[2];
    const float* leaf_bi = (const float*)d_in[4];
    const float* leaf_bh = (const float*)d_in[5];
    const float* node_Wh = (const float*)d_in[7];
    const float* node_bi = (const float*)d_in[8];
    const float* node_bh = (const float*)d_in[9];
    const float* ch_Wi   = (const float*)d_in[10];
    const float* ch_Wh   = (const float*)d_in[11];
    const float* ch_bi   = (const float*)d_in[12];
    const float* ch_bh   = (const float*)d_in[13];

    float *pWl, *pWci, *pWch, *pWn;
    cudaGetSymbolAddress((void**)&pWl,  g_Wl);
    cudaGetSymbolAddress((void**)&pWci, g_Wci);
    cudaGetSymbolAddress((void**)&pWch, g_Wch);
    cudaGetSymbolAddress((void**)&pWn,  g_Wn);

    cudaFuncSetAttribute(gemm_gru<0,LEAF_IN>, cudaFuncAttributeMaxDynamicSharedMemorySize, SMEM_SZ);
    cudaFuncSetAttribute(gemm_gru<1,CH_IN>,   cudaFuncAttributeMaxDynamicSharedMemorySize, SMEM_SZ);
    cudaFuncSetAttribute(gemm_gru<2,MEM>,     cudaFuncAttributeMaxDynamicSharedMemorySize, SMEM_SZ);
    cudaFuncSetAttribute(gemm_gru<3,MEM>,     cudaFuncAttributeMaxDynamicSharedMemorySize, SMEM_SZ);

    auto grid = [](int M) { return dim3(MEM / 64, (M + 63) / 64); };
    float* out = (float*)d_out;

    prep_round<<<2048, 256>>>(embs, tags, leaf_Wi, ch_Wi, ch_Wh, node_Wh);

    gemm_gru<0,LEAF_IN><<<grid(LEAVES), 256, SMEM_SZ>>>(pWl, leaf_bi, leaf_bh, LEAVES, 0, out);
    for (int lvl = DEPTH - 1; lvl >= 0; --lvl) {
        int n = 1 << lvl;
        gemm_gru<1,CH_IN><<<grid(2 * n), 256, SMEM_SZ>>>(pWci, ch_bi, ch_bh, 2 * n, n, out);
        gemm_gru<2,MEM><<<grid(n), 256, SMEM_SZ>>>(pWch, ch_bi, ch_bh, n, n, out);
        gemm_gru<3,MEM><<<grid(n), 256, SMEM_SZ>>>(pWn, node_bi, node_bh, n, n, out);
    }
}

// round 12
// speedup vs baseline: 2.2425x; 2.2425x over previous
#include <cuda_runtime.h>
#include <cuda_fp16.h>
#include <cstdint>
#include <math.h>

#define DEPTH   14
#define LEAVES  16384
#define NNODES  32767
#define MEM     512
#define G3      1536
#define WORD    300
#define TAG     100
#define LEAF_IN 400
#define CH_IN   712

// ---------------- scratch (device globals) -----------------------------------
__device__ float  g_Gi[(size_t)LEAVES * G3];            // right-child preacts (odd rows), fp32
__device__ float  g_H32 [(size_t)(LEAVES / 2) * MEM];   // h1 fp32 (epilogue h_prev)
__device__ float  g_H232[(size_t)(LEAVES / 2) * MEM];   // h2 fp32
__device__ __half g_states16[(size_t)NNODES * MEM];     // states fp16 (GEMM input)
__device__ __half g_H16 [(size_t)(LEAVES / 2) * MEM];   // h1 fp16
__device__ __half g_H216[(size_t)(LEAVES / 2) * MEM];   // h2 fp16
__device__ __half g_leafx16[(size_t)LEAVES * LEAF_IN];  // concat(emb, leaf tag)
__device__ __half g_tagp16[(size_t)NNODES * (2 * TAG)]; // concat(tag, parent tag)
__device__ __half g_Wl16 [(size_t)G3 * LEAF_IN];
__device__ __half g_Wci16[(size_t)G3 * CH_IN];
__device__ __half g_Wch16[(size_t)G3 * MEM];
__device__ __half g_Wn16 [(size_t)G3 * MEM];

__device__ __forceinline__ float sigmoidf(float x) { return 1.0f / (1.0f + expf(-x)); }

__device__ __forceinline__ void mma_f16(float* c, const uint32_t* a, const uint32_t* b) {
    asm volatile(
        "mma.sync.aligned.m16n8k16.row.col.f32.f16.f16.f32 "
        "{%0,%1,%2,%3}, {%4,%5,%6,%7}, {%8,%9}, {%0,%1,%2,%3};"
        : "+f"(c[0]), "+f"(c[1]), "+f"(c[2]), "+f"(c[3])
        : "r"(a[0]), "r"(a[1]), "r"(a[2]), "r"(a[3]), "r"(b[0]), "r"(b[1]));
}
__device__ __forceinline__ void ldsm4(uint32_t* r, uint32_t addr) {
    asm volatile("ldmatrix.sync.aligned.m8n8.x4.shared.b16 {%0,%1,%2,%3}, [%4];"
                 : "=r"(r[0]), "=r"(r[1]), "=r"(r[2]), "=r"(r[3]) : "r"(addr));
}
__device__ __forceinline__ uint32_t smem_u32(const void* p) {
    uint32_t a;
    asm("{ .reg .u64 t; cvta.to.shared.u64 t, %1; cvt.u32.u64 %0, t; }" : "=r"(a) : "l"(p));
    return a;
}
__device__ __forceinline__ void cp16(uint32_t dst, const void* src, int sz) {
    asm volatile("cp.async.cg.shared.global [%0], [%1], 16, %2;"
                 :: "r"(dst), "l"(src), "r"(sz) : "memory");
}
#define CP_COMMIT() asm volatile("cp.async.commit_group;" ::: "memory")
#define CP_WAIT1()  asm volatile("cp.async.wait_group 1;" ::: "memory")

// ---------------- fused GEMM + GRU kernel (round-7 skeleton, fp16 MMA) ----------
// 64-row x 64-gate-col tile; B tile = W rows {k, 512+k, 1024+k} (192 rows).
// BK = 64 halves (128 B/row), row stride 72 halves = 144 B (conflict-free).
// MODE: 0=leaf, 1=ch_Wi (h1 even / gi odd), 2=ch_Wh (h2), 3=node_Wh (states).
#define STAGE_B  36864u                 // 256 rows * 144 B
#define BOFF     9216u                  // A region = 64 * 144
#define SMEM_SZ  (3 * 36864)

template<int MODE, int K>
__global__ __launch_bounds__(256, 2)
void gemm_gru(const __half* __restrict__ Wr, const float* __restrict__ bi,
              const float* __restrict__ bh, int M, int nlvl, float* __restrict__ out) {
    extern __shared__ float sm[];
    constexpr int NC = (K + 63) / 64;

    const int tid  = threadIdx.x;
    const int lane = tid & 31;
    const int wid  = tid >> 5;
    const int gID  = lane >> 2, tq = lane & 3;
    const int wmRow = (wid >> 2) * 32;
    const int wk    = (wid & 3) * 16;
    const int gk0   = blockIdx.x * 64;
    const int bm    = blockIdx.y * 64;

    float acc[2][6][4];
    #pragma unroll
    for (int a = 0; a < 2; a++)
        #pragma unroll
        for (int b = 0; b < 6; b++)
            #pragma unroll
            for (int c = 0; c < 4; c++) acc[a][b][c] = 0.0f;

    const uint32_t smem_base = smem_u32(sm);
    const int rA0 = tid >> 3;                  // 0..31 (row within 32-row group)
    const int eq  = (tid & 7) * 8;             // half-offset within 64-half chunk
    const uint32_t dstA0 = smem_base + (uint32_t)(rA0 * 144 + (tid & 7) * 16);
    const uint32_t dstB0 = smem_base + BOFF + (uint32_t)(rA0 * 144 + (tid & 7) * 16);
    uint32_t offB[6];
    #pragma unroll
    for (int it = 0; it < 6; it++) {
        int rB = rA0 + 32 * it;                // 0..191
        int grow = (rB >> 6) * MEM + gk0 + (rB & 63);
        offB[it] = (uint32_t)grow * K + eq;
    }

    // ldmatrix addresses (byte-identical layout to the proven tf32 kernel)
    uint32_t aAddr[2];
    #pragma unroll
    for (int mt = 0; mt < 2; mt++)
        aAddr[mt] = smem_base + (uint32_t)((wmRow + mt * 16 + (lane & 15)) * 144 + (lane >> 4) * 16);
    uint32_t bAddr[3];
    #pragma unroll
    for (int g = 0; g < 3; g++)
        bAddr[g] = smem_base + BOFF +
                   (uint32_t)((g * 64 + wk + ((lane >> 4) << 3) + (lane & 7)) * 144 + ((lane >> 3) & 1) * 16);

    auto issueA = [&](int kc, uint32_t stN) {
        #pragma unroll
        for (int it = 0; it < 2; it++) {
            const int e  = kc * 64 + eq;       // half index
            const int gm = bm + rA0 + 32 * it;
            const void* p = g_leafx16;
            int sz = 0;
            if (MODE == 0) {
                if (gm < M && e < LEAF_IN) { p = g_leafx16 + (size_t)gm * LEAF_IN + e; sz = 16; }
            } else if (MODE == 1) {
                if (gm < M) {
                    int pid = (gm >> 1) + nlvl - 1;
                    int ch  = 2 * pid + 1 + (gm & 1);
                    if (e < MEM)        { p = g_states16 + (size_t)ch * MEM + e; sz = 16; }
                    else if (e < CH_IN) { p = g_tagp16 + (size_t)ch * (2 * TAG) + (e - MEM); sz = 16; }
                }
            } else {
                const __half* src = (MODE == 2) ? g_H16 : g_H216;
                if (gm < M && e < MEM) { p = src + (size_t)gm * MEM + e; sz = 16; }
            }
            cp16(dstA0 + stN + it * 4608u, p, sz);
        }
    };
    auto issueB = [&](int kc, uint32_t stN) {
        const int e = kc * 64 + eq;
        const int sz = (e < K) ? 16 : 0;
        #pragma unroll
        for (int it = 0; it < 6; it++)
            cp16(dstB0 + stN + it * 4608u, Wr + offB[it] + (uint32_t)kc * 64u, sz);
    };

    issueA(0, 0u); issueB(0, 0u); CP_COMMIT();
    if (NC > 1) { issueA(1, STAGE_B); issueB(1, STAGE_B); }
    CP_COMMIT();

    uint32_t stC = 0, stI = 2 * STAGE_B;
    #pragma unroll 1
    for (int kc = 0; kc < NC; kc++) {
        CP_WAIT1();
        __syncthreads();
        if (kc + 2 < NC) { issueA(kc + 2, stI); issueB(kc + 2, stI); }
        CP_COMMIT();
        #pragma unroll
        for (int k16 = 0; k16 < 4; k16++) {        // 4 x k16 = 64 halves
            const uint32_t kb = stC + k16 * 32u;   // 16 halves = 32 bytes
            uint32_t afr[2][4], bfr[3][4];
            ldsm4(afr[0], aAddr[0] + kb);
            ldsm4(afr[1], aAddr[1] + kb);
            ldsm4(bfr[0], bAddr[0] + kb);
            ldsm4(bfr[1], bAddr[1] + kb);
            ldsm4(bfr[2], bAddr[2] + kb);
            #pragma unroll
            for (int mt = 0; mt < 2; mt++)
                #pragma unroll
                for (int g = 0; g < 3; g++) {
                    mma_f16(acc[mt][2 * g],     afr[mt], bfr[g]);       // kt=0 (n0..n0+7)
                    mma_f16(acc[mt][2 * g + 1], afr[mt], bfr[g] + 2);   // kt=1 (n0+8..15)
                }
        }
        stC += STAGE_B; if (stC == 3 * STAGE_B) stC = 0;
        stI += STAGE_B; if (stI == 3 * STAGE_B) stI = 0;
    }

    // ---- fused epilogue ----
    #pragma unroll
    for (int mt = 0; mt < 2; mt++)
        #pragma unroll
        for (int kt = 0; kt < 2; kt++)
            #pragma unroll
            for (int j = 0; j < 4; j++) {
                int row = bm + wmRow + mt * 16 + gID + (j >> 1) * 8;
                if (row >= M) continue;
                int kcol = gk0 + wk + kt * 8 + 2 * tq + (j & 1);
                float aR = acc[mt][kt][j];
                float aZ = acc[mt][2 + kt][j];
                float aN = acc[mt][4 + kt][j];
                if (MODE == 0) {
                    float r  = sigmoidf(aR + bi[kcol] + bh[kcol]);
                    float z  = sigmoidf(aZ + bi[MEM + kcol] + bh[MEM + kcol]);
                    float nn = tanhf(aN + bi[2 * MEM + kcol] + r * bh[2 * MEM + kcol]);
                    g_states16[(size_t)(LEAVES - 1 + row) * MEM + kcol] =
                        __float2half((1.0f - z) * nn);
                } else if (MODE == 1) {
                    float giR = aR + bi[kcol], giZ = aZ + bi[MEM + kcol],
                          giN = aN + bi[2 * MEM + kcol];
                    if ((row & 1) == 0) {
                        float r  = sigmoidf(giR + bh[kcol]);
                        float z  = sigmoidf(giZ + bh[MEM + kcol]);
                        float nn = tanhf(giN + r * bh[2 * MEM + kcol]);
                        float h1 = (1.0f - z) * nn;
                        size_t idx = (size_t)(row >> 1) * MEM + kcol;
                        g_H32[idx] = h1;
                        g_H16[idx] = __float2half(h1);
                    } else {
                        float* d = g_Gi + (size_t)row * G3;
                        d[kcol] = giR; d[MEM + kcol] = giZ; d[2 * MEM + kcol] = giN;
                    }
                } else if (MODE == 2) {
                    const float* gi = g_Gi + (size_t)(2 * row + 1) * G3;
                    float r  = sigmoidf(gi[kcol] + aR + bh[kcol]);
                    float z  = sigmoidf(gi[MEM + kcol] + aZ + bh[MEM + kcol]);
                    float nn = tanhf(gi[2 * MEM + kcol] + r * (aN + bh[2 * MEM + kcol]));
                    size_t idx = (size_t)row * MEM + kcol;
                    float h2 = (1.0f - z) * nn + z * g_H32[idx];
                    g_H232[idx] = h2;
                    g_H216[idx] = __float2half(h2);
                } else {
                    float r  = sigmoidf(bi[kcol] + aR + bh[kcol]);
                    float z  = sigmoidf(bi[MEM + kcol] + aZ + bh[MEM + kcol]);
                    float nn = tanhf(bi[2 * MEM + kcol] + r * (aN + bh[2 * MEM + kcol]));
                    float st = (1.0f - z) * nn + z * g_H232[(size_t)row * MEM + kcol];
                    g_states16[(size_t)(row + nlvl - 1) * MEM + kcol] = __float2half(st);
                    if (nlvl == 1) out[kcol] = st;
                }
            }
}

// ---------------- prep: build fp16 operands ------------------------------------
__global__ void prep_half(const float* __restrict__ embs, const float* __restrict__ tags,
                          const float* __restrict__ lw, const float* __restrict__ cwi,
                          const float* __restrict__ cwh, const float* __restrict__ nw) {
    const int64_t stride = (int64_t)gridDim.x * blockDim.x;
    const int64_t t0 = blockIdx.x * (int64_t)blockDim.x + threadIdx.x;
    // leafx: concat(emb, leaf tag)
    for (int64_t i = t0; i < (int64_t)LEAVES * LEAF_IN; i += stride) {
        int r = (int)(i / LEAF_IN), c = (int)(i % LEAF_IN);
        float v = (c < WORD) ? embs[(size_t)r * WORD + c]
                             : tags[(size_t)(LEAVES - 1 + r) * TAG + (c - WORD)];
        g_leafx16[i] = __float2half(v);
    }
    // tagp: concat(tag, parent tag)
    for (int64_t i = t0; i < (int64_t)NNODES * 2 * TAG; i += stride) {
        int id = (int)(i / (2 * TAG)), c = (int)(i % (2 * TAG));
        int pid = (id > 0) ? ((id - 1) >> 1) : 0;
        float v = (c < TAG) ? tags[(size_t)id * TAG + c]
                            : tags[(size_t)pid * TAG + (c - TAG)];
        g_tagp16[i] = __float2half(v);
    }
    for (int64_t i = t0; i < (int64_t)G3 * LEAF_IN; i += stride) g_Wl16[i]  = __float2half(lw[i]);
    for (int64_t i = t0; i < (int64_t)G3 * CH_IN;  i += stride) g_Wci16[i] = __float2half(cwi[i]);
    for (int64_t i = t0; i < (int64_t)G3 * MEM;    i += stride) g_Wch16[i] = __float2half(cwh[i]);
    for (int64_t i = t0; i < (int64_t)G3 * MEM;    i += stride) g_Wn16[i]  = __float2half(nw[i]);
}

// ---------------- host driver ------------------------------------------------
extern "C" void kernel_launch(void* const* d_in, const int* in_sizes, int n_in,
                              void* d_out, int out_size) {
    const float* embs    = (const float*)d_in[0];
    const float* tags    = (const float*)d_in[1];
    const float* leaf_Wi = (const float*)d_in[2];
    const float* leaf_bi = (const float*)d_in[4];
    const float* leaf_bh = (const float*)d_in[5];
    const float* node_Wh = (const float*)d_in[7];
    const float* node_bi = (const float*)d_in[8];
    const float* node_bh = (const float*)d_in[9];
    const float* ch_Wi   = (const float*)d_in[10];
    const float* ch_Wh   = (const float*)d_in[11];
    const float* ch_bi   = (const float*)d_in[12];
    const float* ch_bh   = (const float*)d_in[13];

    __half *pWl, *pWci, *pWch, *pWn;
    cudaGetSymbolAddress((void**)&pWl,  g_Wl16);
    cudaGetSymbolAddress((void**)&pWci, g_Wci16);
    cudaGetSymbolAddress((void**)&pWch, g_Wch16);
    cudaGetSymbolAddress((void**)&pWn,  g_Wn16);

    cudaFuncSetAttribute(gemm_gru<0,LEAF_IN>, cudaFuncAttributeMaxDynamicSharedMemorySize, SMEM_SZ);
    cudaFuncSetAttribute(gemm_gru<1,CH_IN>,   cudaFuncAttributeMaxDynamicSharedMemorySize, SMEM_SZ);
    cudaFuncSetAttribute(gemm_gru<2,MEM>,     cudaFuncAttributeMaxDynamicSharedMemorySize, SMEM_SZ);
    cudaFuncSetAttribute(gemm_gru<3,MEM>,     cudaFuncAttributeMaxDynamicSharedMemorySize, SMEM_SZ);

    auto grid = [](int M) { return dim3(MEM / 64, (M + 63) / 64); };
    float* out = (float*)d_out;

    prep_half<<<1024, 256>>>(embs, tags, leaf_Wi, ch_Wi, ch_Wh, node_Wh);

    gemm_gru<0,LEAF_IN><<<grid(LEAVES), 256, SMEM_SZ>>>(pWl, leaf_bi, leaf_bh, LEAVES, 0, out);
    for (int lvl = DEPTH - 1; lvl >= 0; --lvl) {
        int n = 1 << lvl;
        gemm_gru<1,CH_IN><<<grid(2 * n), 256, SMEM_SZ>>>(pWci, ch_bi, ch_bh, 2 * n, n, out);
        gemm_gru<2,MEM><<<grid(n), 256, SMEM_SZ>>>(pWch, ch_bi, ch_bh, n, n, out);
        gemm_gru<3,MEM><<<grid(n), 256, SMEM_SZ>>>(pWn, node_bi, node_bh, n, n, out);
    }
}

// round 13
// speedup vs baseline: 2.6587x; 1.1856x over previous
#include <cuda_runtime.h>
#include <cuda_fp16.h>
#include <cstdint>
#include <math.h>

#define DEPTH   14
#define LEAVES  16384
#define NNODES  32767
#define MEM     512
#define G3      1536
#define WORD    300
#define TAG     100
#define LEAF_IN 400
#define CH_IN   712

// ---------------- scratch (device globals) -----------------------------------
__device__ float  g_Gi[(size_t)LEAVES * G3];            // right-child preacts (odd rows), fp32
__device__ float  g_H32 [(size_t)(LEAVES / 2) * MEM];   // h1 fp32
__device__ float  g_H232[(size_t)(LEAVES / 2) * MEM];   // h2 fp32
__device__ __half g_states16[(size_t)NNODES * MEM];
__device__ __half g_H16 [(size_t)(LEAVES / 2) * MEM];
__device__ __half g_H216[(size_t)(LEAVES / 2) * MEM];
__device__ __half g_leafx16[(size_t)LEAVES * LEAF_IN];
__device__ __half g_tagp16[(size_t)NNODES * (2 * TAG)];
__device__ __half g_Wl16 [(size_t)G3 * LEAF_IN];
__device__ __half g_Wci16[(size_t)G3 * CH_IN];
__device__ __half g_Wch16[(size_t)G3 * MEM];
__device__ __half g_Wn16 [(size_t)G3 * MEM];

__device__ __forceinline__ float sigmoidf(float x) { return 1.0f / (1.0f + expf(-x)); }

__device__ __forceinline__ void mma_f16(float* c, const uint32_t* a, const uint32_t* b) {
    asm volatile(
        "mma.sync.aligned.m16n8k16.row.col.f32.f16.f16.f32 "
        "{%0,%1,%2,%3}, {%4,%5,%6,%7}, {%8,%9}, {%0,%1,%2,%3};"
        : "+f"(c[0]), "+f"(c[1]), "+f"(c[2]), "+f"(c[3])
        : "r"(a[0]), "r"(a[1]), "r"(a[2]), "r"(a[3]), "r"(b[0]), "r"(b[1]));
}
__device__ __forceinline__ void ldsm4(uint32_t* r, uint32_t addr) {
    asm volatile("ldmatrix.sync.aligned.m8n8.x4.shared.b16 {%0,%1,%2,%3}, [%4];"
                 : "=r"(r[0]), "=r"(r[1]), "=r"(r[2]), "=r"(r[3]) : "r"(addr));
}
__device__ __forceinline__ void ldsm2(uint32_t* r, uint32_t addr) {
    asm volatile("ldmatrix.sync.aligned.m8n8.x2.shared.b16 {%0,%1}, [%2];"
                 : "=r"(r[0]), "=r"(r[1]) : "r"(addr));
}
__device__ __forceinline__ uint32_t smem_u32(const void* p) {
    uint32_t a;
    asm("{ .reg .u64 t; cvta.to.shared.u64 t, %1; cvt.u32.u64 %0, t; }" : "=r"(a) : "l"(p));
    return a;
}
__device__ __forceinline__ void cp16(uint32_t dst, const void* src, int sz) {
    asm volatile("cp.async.cg.shared.global [%0], [%1], 16, %2;"
                 :: "r"(dst), "l"(src), "r"(sz) : "memory");
}
#define CP_COMMIT() asm volatile("cp.async.commit_group;" ::: "memory")
#define CP_WAIT1()  asm volatile("cp.async.wait_group 1;" ::: "memory")

// ---------------- fused GEMM + GRU kernel: 64 x 32-gate-col tile ----------------
// B tile = W rows {k, 512+k, 1024+k} for 32 kcols -> 96 rows; A tile 64 rows.
// BK = 64 halves (128 B + 16 pad = 144 B row stride). 3 stages, 3 CTAs/SM.
// MODE: 0=leaf, 1=ch_Wi (h1 even / gi odd), 2=ch_Wh (h2), 3=node_Wh (states).
#define STAGE_B  23040u                 // (64 + 96) rows * 144 B
#define BOFF     9216u                  // A region = 64 * 144
#define SMEM_SZ  (3 * 23040)

template<int MODE, int K>
__global__ __launch_bounds__(256, 3)
void gemm_gru(const __half* __restrict__ Wr, const float* __restrict__ bi,
              const float* __restrict__ bh, int M, int nlvl, float* __restrict__ out) {
    extern __shared__ float sm[];
    constexpr int NC = (K + 63) / 64;

    const int tid  = threadIdx.x;
    const int lane = tid & 31;
    const int wid  = tid >> 5;
    const int gID  = lane >> 2, tq = lane & 3;
    const int wmRow = (wid >> 2) * 32;         // 0 / 32
    const int wk    = (wid & 3) * 8;           // 0..24 within 32 gate-cols
    const int gk0   = blockIdx.x * 32;
    const int bm    = blockIdx.y * 64;

    float acc[2][3][4];
    #pragma unroll
    for (int a = 0; a < 2; a++)
        #pragma unroll
        for (int b = 0; b < 3; b++)
            #pragma unroll
            for (int c = 0; c < 4; c++) acc[a][b][c] = 0.0f;

    const uint32_t smem_base = smem_u32(sm);
    const int rA0 = tid >> 3;                  // 0..31
    const int eq  = (tid & 7) * 8;             // half-offset within 64-half chunk
    const uint32_t dstA0 = smem_base + (uint32_t)(rA0 * 144 + (tid & 7) * 16);
    const uint32_t dstB0 = smem_base + BOFF + (uint32_t)(rA0 * 144 + (tid & 7) * 16);
    uint32_t offB[3];
    #pragma unroll
    for (int it = 0; it < 3; it++) {
        int rB = rA0 + 32 * it;                // 0..95
        int grow = (rB >> 5) * MEM + gk0 + (rB & 31);
        offB[it] = (uint32_t)grow * K + eq;
    }

    uint32_t aAddr[2];
    #pragma unroll
    for (int mt = 0; mt < 2; mt++)
        aAddr[mt] = smem_base + (uint32_t)((wmRow + mt * 16 + (lane & 15)) * 144 + (lane >> 4) * 16);
    uint32_t bAddr[3];
    #pragma unroll
    for (int g = 0; g < 3; g++)
        bAddr[g] = smem_base + BOFF +
                   (uint32_t)((g * 32 + wk + (lane & 7)) * 144 + (((lane >> 3) & 1) * 16));

    auto issueA = [&](int kc, uint32_t stN) {
        #pragma unroll
        for (int it = 0; it < 2; it++) {
            const int e  = kc * 64 + eq;
            const int gm = bm + rA0 + 32 * it;
            const void* p = g_leafx16;
            int sz = 0;
            if (MODE == 0) {
                if (gm < M && e < LEAF_IN) { p = g_leafx16 + (size_t)gm * LEAF_IN + e; sz = 16; }
            } else if (MODE == 1) {
                if (gm < M) {
                    int pid = (gm >> 1) + nlvl - 1;
                    int ch  = 2 * pid + 1 + (gm & 1);
                    if (e < MEM)        { p = g_states16 + (size_t)ch * MEM + e; sz = 16; }
                    else if (e < CH_IN) { p = g_tagp16 + (size_t)ch * (2 * TAG) + (e - MEM); sz = 16; }
                }
            } else {
                const __half* src = (MODE == 2) ? g_H16 : g_H216;
                if (gm < M && e < MEM) { p = src + (size_t)gm * MEM + e; sz = 16; }
            }
            cp16(dstA0 + stN + it * 4608u, p, sz);
        }
    };
    auto issueB = [&](int kc, uint32_t stN) {
        const int e = kc * 64 + eq;
        const int sz = (e < K) ? 16 : 0;
        #pragma unroll
        for (int it = 0; it < 3; it++)
            cp16(dstB0 + stN + it * 4608u, Wr + offB[it] + (uint32_t)kc * 64u, sz);
    };

    issueA(0, 0u); issueB(0, 0u); CP_COMMIT();
    if (NC > 1) { issueA(1, STAGE_B); issueB(1, STAGE_B); }
    CP_COMMIT();

    uint32_t stC = 0, stI = 2 * STAGE_B;
    #pragma unroll 1
    for (int kc = 0; kc < NC; kc++) {
        CP_WAIT1();
        __syncthreads();
        if (kc + 2 < NC) { issueA(kc + 2, stI); issueB(kc + 2, stI); }
        CP_COMMIT();
        #pragma unroll
        for (int k16 = 0; k16 < 4; k16++) {        // 4 x k16 = 64 halves
            const uint32_t kb = stC + k16 * 32u;
            uint32_t afr[2][4], bfr[3][2];
            ldsm4(afr[0], aAddr[0] + kb);
            ldsm4(afr[1], aAddr[1] + kb);
            ldsm2(bfr[0], bAddr[0] + kb);
            ldsm2(bfr[1], bAddr[1] + kb);
            ldsm2(bfr[2], bAddr[2] + kb);
            #pragma unroll
            for (int mt = 0; mt < 2; mt++)
                #pragma unroll
                for (int g = 0; g < 3; g++)
                    mma_f16(acc[mt][g], afr[mt], bfr[g]);
        }
        stC += STAGE_B; if (stC == 3 * STAGE_B) stC = 0;
        stI += STAGE_B; if (stI == 3 * STAGE_B) stI = 0;
    }

    // ---- fused epilogue ----
    #pragma unroll
    for (int mt = 0; mt < 2; mt++)
        #pragma unroll
        for (int j = 0; j < 4; j++) {
            int row = bm + wmRow + mt * 16 + gID + (j >> 1) * 8;
            if (row >= M) continue;
            int kcol = gk0 + wk + 2 * tq + (j & 1);
            float aR = acc[mt][0][j];
            float aZ = acc[mt][1][j];
            float aN = acc[mt][2][j];
            if (MODE == 0) {
                float r  = sigmoidf(aR + bi[kcol] + bh[kcol]);
                float z  = sigmoidf(aZ + bi[MEM + kcol] + bh[MEM + kcol]);
                float nn = tanhf(aN + bi[2 * MEM + kcol] + r * bh[2 * MEM + kcol]);
                g_states16[(size_t)(LEAVES - 1 + row) * MEM + kcol] =
                    __float2half((1.0f - z) * nn);
            } else if (MODE == 1) {
                float giR = aR + bi[kcol], giZ = aZ + bi[MEM + kcol],
                      giN = aN + bi[2 * MEM + kcol];
                if ((row & 1) == 0) {
                    float r  = sigmoidf(giR + bh[kcol]);
                    float z  = sigmoidf(giZ + bh[MEM + kcol]);
                    float nn = tanhf(giN + r * bh[2 * MEM + kcol]);
                    float h1 = (1.0f - z) * nn;
                    size_t idx = (size_t)(row >> 1) * MEM + kcol;
                    g_H32[idx] = h1;
                    g_H16[idx] = __float2half(h1);
                } else {
                    float* d = g_Gi + (size_t)row * G3;
                    d[kcol] = giR; d[MEM + kcol] = giZ; d[2 * MEM + kcol] = giN;
                }
            } else if (MODE == 2) {
                const float* gi = g_Gi + (size_t)(2 * row + 1) * G3;
                float r  = sigmoidf(gi[kcol] + aR + bh[kcol]);
                float z  = sigmoidf(gi[MEM + kcol] + aZ + bh[MEM + kcol]);
                float nn = tanhf(gi[2 * MEM + kcol] + r * (aN + bh[2 * MEM + kcol]));
                size_t idx = (size_t)row * MEM + kcol;
                float h2 = (1.0f - z) * nn + z * g_H32[idx];
                g_H232[idx] = h2;
                g_H216[idx] = __float2half(h2);
            } else {
                float r  = sigmoidf(bi[kcol] + aR + bh[kcol]);
                float z  = sigmoidf(bi[MEM + kcol] + aZ + bh[MEM + kcol]);
                float nn = tanhf(bi[2 * MEM + kcol] + r * (aN + bh[2 * MEM + kcol]));
                float st = (1.0f - z) * nn + z * g_H232[(size_t)row * MEM + kcol];
                g_states16[(size_t)(row + nlvl - 1) * MEM + kcol] = __float2half(st);
                if (nlvl == 1) out[kcol] = st;
            }
        }
}

// ---------------- prep: build fp16 operands ------------------------------------
__global__ void prep_half(const float* __restrict__ embs, const float* __restrict__ tags,
                          const float* __restrict__ lw, const float* __restrict__ cwi,
                          const float* __restrict__ cwh, const float* __restrict__ nw) {
    const int64_t stride = (int64_t)gridDim.x * blockDim.x;
    const int64_t t0 = blockIdx.x * (int64_t)blockDim.x + threadIdx.x;
    for (int64_t i = t0; i < (int64_t)LEAVES * LEAF_IN; i += stride) {
        int r = (int)(i / LEAF_IN), c = (int)(i % LEAF_IN);
        float v = (c < WORD) ? embs[(size_t)r * WORD + c]
                             : tags[(size_t)(LEAVES - 1 + r) * TAG + (c - WORD)];
        g_leafx16[i] = __float2half(v);
    }
    for (int64_t i = t0; i < (int64_t)NNODES * 2 * TAG; i += stride) {
        int id = (int)(i / (2 * TAG)), c = (int)(i % (2 * TAG));
        int pid = (id > 0) ? ((id - 1) >> 1) : 0;
        float v = (c < TAG) ? tags[(size_t)id * TAG + c]
                            : tags[(size_t)pid * TAG + (c - TAG)];
        g_tagp16[i] = __float2half(v);
    }
    for (int64_t i = t0; i < (int64_t)G3 * LEAF_IN; i += stride) g_Wl16[i]  = __float2half(lw[i]);
    for (int64_t i = t0; i < (int64_t)G3 * CH_IN;  i += stride) g_Wci16[i] = __float2half(cwi[i]);
    for (int64_t i = t0; i < (int64_t)G3 * MEM;    i += stride) g_Wch16[i] = __float2half(cwh[i]);
    for (int64_t i = t0; i < (int64_t)G3 * MEM;    i += stride) g_Wn16[i]  = __float2half(nw[i]);
}

// ---------------- host driver ------------------------------------------------
extern "C" void kernel_launch(void* const* d_in, const int* in_sizes, int n_in,
                              void* d_out, int out_size) {
    const float* embs    = (const float*)d_in[0];
    const float* tags    = (const float*)d_in[1];
    const float* leaf_Wi = (const float*)d_in[2];
    const float* leaf_bi = (const float*)d_in[4];
    const float* leaf_bh = (const float*)d_in[5];
    const float* node_Wh = (const float*)d_in[7];
    const float* node_bi = (const float*)d_in[8];
    const float* node_bh = (const float*)d_in[9];
    const float* ch_Wi   = (const float*)d_in[10];
    const float* ch_Wh   = (const float*)d_in[11];
    const float* ch_bi   = (const float*)d_in[12];
    const float* ch_bh   = (const float*)d_in[13];

    __half *pWl, *pWci, *pWch, *pWn;
    cudaGetSymbolAddress((void**)&pWl,  g_Wl16);
    cudaGetSymbolAddress((void**)&pWci, g_Wci16);
    cudaGetSymbolAddress((void**)&pWch, g_Wch16);
    cudaGetSymbolAddress((void**)&pWn,  g_Wn16);

    cudaFuncSetAttribute(gemm_gru<0,LEAF_IN>, cudaFuncAttributeMaxDynamicSharedMemorySize, SMEM_SZ);
    cudaFuncSetAttribute(gemm_gru<1,CH_IN>,   cudaFuncAttributeMaxDynamicSharedMemorySize, SMEM_SZ);
    cudaFuncSetAttribute(gemm_gru<2,MEM>,     cudaFuncAttributeMaxDynamicSharedMemorySize, SMEM_SZ);
    cudaFuncSetAttribute(gemm_gru<3,MEM>,     cudaFuncAttributeMaxDynamicSharedMemorySize, SMEM_SZ);

    auto grid = [](int M) { return dim3(MEM / 32, (M + 63) / 64); };
    float* out = (float*)d_out;

    prep_half<<<1024, 256>>>(embs, tags, leaf_Wi, ch_Wi, ch_Wh, node_Wh);

    gemm_gru<0,LEAF_IN><<<grid(LEAVES), 256, SMEM_SZ>>>(pWl, leaf_bi, leaf_bh, LEAVES, 0, out);
    for (int lvl = DEPTH - 1; lvl >= 0; --lvl) {
        int n = 1 << lvl;
        gemm_gru<1,CH_IN><<<grid(2 * n), 256, SMEM_SZ>>>(pWci, ch_bi, ch_bh, 2 * n, n, out);
        gemm_gru<2,MEM><<<grid(n), 256, SMEM_SZ>>>(pWch, ch_bi, ch_bh, n, n, out);
        gemm_gru<3,MEM><<<grid(n), 256, SMEM_SZ>>>(pWn, node_bi, node_bh, n, n, out);
    }
}